// round 4
// baseline (speedup 1.0000x reference)
#include <cuda_runtime.h>
#include <math.h>

// MarginalGaussianization forward on GB300.
// Inputs (metadata order): x [B,64] f32, x_values [64,1000] f32 (sorted per row),
// cdf_values [64,1000] f32 (strictly increasing). Output: z [B,64] then log_det [B].
//
// Strategy:
//  - 8 dim-groups x 18 sample-chunks = 144 blocks (single wave on 148 SMs).
//  - Each block builds an 8-dim bin table in shared memory:
//      ent[j] = (x_l, slope, c_l, log(p_hat)+log(sqrt(2*pi)))
//    so the per-element hot path is: analytic bin guess + exact fixup (LDS),
//    u = fma(slope, x-x_l, c_l), erfinv (Giles poly), term = L + 0.5*z*z.
//  - Per-group partial log-det -> __device__ scratch, reduced by a tiny 2nd kernel.

#define DIMS    64
#define NBK     1000
#define GROUPS  8
#define DPG     8              // dims per group
#define TPB     512
#define NCHUNK  18
#define BMAX    262144

__device__ float g_partial[GROUPS * (size_t)BMAX];

__device__ __forceinline__ float erfinv_giles(float t) {
    // t in [-0.99999, 0.99999] (pre-clamped). Same algorithm XLA uses for f32 erfinv.
    float w = -__logf(fmaf(t, -t, 1.0f));   // -log(1 - t^2), w <= ~10.8
    float p;
    if (w < 5.0f) {
        w -= 2.5f;
        p =              2.81022636e-08f;
        p = fmaf(p, w,   3.43273939e-07f);
        p = fmaf(p, w,  -3.5233877e-06f);
        p = fmaf(p, w,  -4.39150654e-06f);
        p = fmaf(p, w,   0.00021858087f);
        p = fmaf(p, w,  -0.00125372503f);
        p = fmaf(p, w,  -0.00417768164f);
        p = fmaf(p, w,   0.246640727f);
        p = fmaf(p, w,   1.50140941f);
    } else {
        w = sqrtf(w) - 3.0f;
        p =             -0.000200214257f;
        p = fmaf(p, w,   0.000100950558f);
        p = fmaf(p, w,   0.00134934322f);
        p = fmaf(p, w,  -0.00367342844f);
        p = fmaf(p, w,   0.00573950773f);
        p = fmaf(p, w,  -0.0076224613f);
        p = fmaf(p, w,   0.00943887047f);
        p = fmaf(p, w,   1.00167406f);
        p = fmaf(p, w,   2.83297682f);
    }
    return p * t;
}

__global__ __launch_bounds__(TPB)
void mg_main(const float* __restrict__ x,
             const float* __restrict__ xv,
             const float* __restrict__ cdf,
             float* __restrict__ zout,
             int B, int spb)
{
    extern __shared__ float4 tab[];          // [DPG][NBK], 128000 bytes
    __shared__ float2 dinfo_s[DPG];

    const int g  = blockIdx.y;
    const int d0 = g * DPG;

    // ---- Build per-bin payload table in shared memory ----
    for (int idx = threadIdx.x; idx < DPG * NBK; idx += TPB) {
        int k = idx / NBK;
        int j = idx - k * NBK;
        const float* xvk = xv  + (size_t)(d0 + k) * NBK;
        const float* ck  = cdf + (size_t)(d0 + k) * NBK;
        float4 e;
        if (j < NBK - 1) {
            float xl = xvk[j], xr = xvk[j + 1];
            float cl = ck[j],  cr = ck[j + 1];
            float denom = xr - xl + 1e-12f;
            float s = (cr - cl) / denom;                       // matches reference math
            float ph = fmaxf(s, 1e-12f);                       // p_hat
            // term = log(p_hat) - log(phi+1e-12) = [log(p_hat)+log(sqrt(2pi))] + 0.5 z^2
            // (|z| <= 4.42 so phi >> 1e-12; approximation error < 5e-8)
            e = make_float4(xl, s, cl, logf(ph) + 0.91893853320467274f);
        } else {
            e = make_float4(xvk[NBK - 1], 0.f, 0.f, 0.f);      // right edge sentinel
        }
        tab[k * NBK + j] = e;
    }
    if (threadIdx.x < DPG) {
        const float* xvk = xv + (size_t)(d0 + threadIdx.x) * NBK;
        float x0 = xvk[0], x1 = xvk[NBK - 1];
        dinfo_s[threadIdx.x] = make_float2(x0, (float)(NBK - 1) / (x1 - x0));
    }
    __syncthreads();

    float2 di[DPG];
    #pragma unroll
    for (int k = 0; k < DPG; k++) di[k] = dinfo_s[k];

    const int b0   = blockIdx.x * spb;
    const int bend = min(B, b0 + spb);

    for (int b = b0 + (int)threadIdx.x; b < bend; b += TPB) {
        const float4* xp = (const float4*)(x + (size_t)b * DIMS + d0);
        float4 xa = xp[0];
        float4 xb = xp[1];
        float xs8[8] = {xa.x, xa.y, xa.z, xa.w, xb.x, xb.y, xb.z, xb.w};
        float zs8[8];
        float acc = 0.0f;

        #pragma unroll
        for (int k = 0; k < DPG; k++) {
            float xk = xs8[k];
            const float4* tk = tab + k * NBK;

            // analytic bin guess on the (near-)uniform grid
            int j = __float2int_rd((xk - di[k].x) * di[k].y);
            j = max(0, min(j, NBK - 2));

            // exact fixup so that: j == clip(searchsorted_left(xv, xk) - 1, 0, NBK-2)
            // up-phase: need xk <= xv[j+1]  (or j == NBK-2)
            float xr = *((const float*)(tk + j + 1));          // LDS.32 of ent[j+1].x
            while (j < NBK - 2 && xk > xr) { ++j; xr = *((const float*)(tk + j + 1)); }
            float4 e = tk[j];                                  // LDS.128
            // down-phase: need xv[j] < xk  (or j == 0)
            while (j > 0 && xk <= e.x) { --j; e = tk[j]; }

            // u = c_l + slope * (x - x_l); e-clamp subsumes the u-clip in the reference
            float u = fmaf(e.y, xk - e.x, e.z);
            float t = fmaf(2.0f, u, -1.0f);
            t = fminf(fmaxf(t, -0.99999f), 0.99999f);

            float zz = 1.4142135623730951f * erfinv_giles(t);
            zz = fminf(fmaxf(zz, -10.0f), 10.0f);

            acc += fmaf(0.5f * zz, zz, e.w);
            zs8[k] = zz;
        }

        float4* zp = (float4*)(zout + (size_t)b * DIMS + d0);
        zp[0] = make_float4(zs8[0], zs8[1], zs8[2], zs8[3]);
        zp[1] = make_float4(zs8[4], zs8[5], zs8[6], zs8[7]);
        g_partial[(size_t)g * B + b] = acc;
    }
}

__global__ void mg_reduce(float* __restrict__ ld, int B)
{
    int b = blockIdx.x * blockDim.x + threadIdx.x;
    if (b < B) {
        float s = 0.0f;
        #pragma unroll
        for (int g = 0; g < GROUPS; g++) s += g_partial[(size_t)g * B + b];
        ld[b] = s;
    }
}

extern "C" void kernel_launch(void* const* d_in, const int* in_sizes, int n_in,
                              void* d_out, int out_size)
{
    const float* x   = (const float*)d_in[0];
    const float* xv  = (const float*)d_in[1];
    const float* cdf = (const float*)d_in[2];
    float* out = (float*)d_out;

    const int B = in_sizes[0] / DIMS;
    const int spb = (B + NCHUNK - 1) / NCHUNK;
    const size_t smem = (size_t)DPG * NBK * sizeof(float4);   // 128000 B

    // Opt-in to >48KB dynamic shared memory (idempotent; no stream ops, capture-safe).
    cudaFuncSetAttribute(mg_main, cudaFuncAttributeMaxDynamicSharedMemorySize, (int)smem);

    dim3 grid(NCHUNK, GROUPS);
    mg_main<<<grid, TPB, smem>>>(x, xv, cdf, out, B, spb);

    float* ld = out + (size_t)B * DIMS;
    mg_reduce<<<(B + 255) / 256, 256>>>(ld, B);
}

// round 5
// speedup vs baseline: 1.0348x; 1.0348x over previous
#include <cuda_runtime.h>
#include <math.h>

// MarginalGaussianization forward on GB300 — branchless bin lookup version.
// Inputs: x [B,64] f32, x_values [64,1000] f32 (sorted linspace per row),
// cdf_values [64,1000] f32 (strictly increasing). Output: z [B,64] then log_det [B].
//
//  - 8 dim-groups x 18 sample-chunks = 144 blocks (single wave on 148 SMs).
//  - smem per block: payload float4[8][1000] (x_l, slope, c_l, L) = 128000 B
//                  + xv float[8][1000] (stride-4 for conflict-free fixup) = 32000 B
//  - Hot path per element (NO branches): analytic bin guess (linspace inverse),
//    exact +/-1 branchless fixup, LDS.128 payload, fma for u, branchless erfinv,
//    log-det term = L + 0.5*z^2 (exp/log folded into the precomputed table).

#define DIMS    64
#define NBK     1000
#define GROUPS  8
#define DPG     8
#define TPB     512
#define NCHUNK  18
#define BMAX    262144

__device__ float g_partial[GROUPS * (size_t)BMAX];

__global__ __launch_bounds__(TPB)
void mg_main(const float* __restrict__ x,
             const float* __restrict__ xv,
             const float* __restrict__ cdf,
             float* __restrict__ zout,
             int B, int spb)
{
    extern __shared__ char smem_raw[];
    float4* tab = (float4*)smem_raw;                         // [DPG][NBK] payload
    float*  xvs = (float*)(smem_raw + DPG * NBK * 16);       // [DPG][NBK] grid values
    __shared__ float2 dinfo_s[DPG];

    const int g  = blockIdx.y;
    const int d0 = g * DPG;

    // ---- Build per-bin payload + grid tables in shared memory ----
    for (int idx = threadIdx.x; idx < DPG * NBK; idx += TPB) {
        int k = idx / NBK;
        int j = idx - k * NBK;
        const float* xvk = xv  + (size_t)(d0 + k) * NBK;
        const float* ck  = cdf + (size_t)(d0 + k) * NBK;
        float xl = xvk[j];
        xvs[k * NBK + j] = xl;
        float4 e;
        if (j < NBK - 1) {
            float xr = xvk[j + 1];
            float cl = ck[j],  cr = ck[j + 1];
            float denom = xr - xl + 1e-12f;
            float s = (cr - cl) / denom;                     // matches reference math
            float ph = fmaxf(s, 1e-12f);                     // p_hat
            // term = log(p_hat) - log(phi + 1e-12)
            //      = [log(p_hat) + log(sqrt(2*pi))] + 0.5*z^2   (|z| <= 4.42, err < 5e-8)
            e = make_float4(xl, s, cl, logf(ph) + 0.91893853320467274f);
            tab[k * NBK + j] = e;
        }
    }
    if (threadIdx.x < DPG) {
        const float* xvk = xv + (size_t)(d0 + threadIdx.x) * NBK;
        float x0 = xvk[0], x1 = xvk[NBK - 1];
        dinfo_s[threadIdx.x] = make_float2(x0, (float)(NBK - 1) / (x1 - x0));
    }
    __syncthreads();

    float2 di[DPG];
    #pragma unroll
    for (int k = 0; k < DPG; k++) di[k] = dinfo_s[k];

    const int b0   = blockIdx.x * spb;
    const int bend = min(B, b0 + spb);

    for (int b = b0 + (int)threadIdx.x; b < bend; b += TPB) {
        const float4* xp = (const float4*)(x + (size_t)b * DIMS + d0);
        float4 xa = xp[0];
        float4 xb = xp[1];
        float xs8[8] = {xa.x, xa.y, xa.z, xa.w, xb.x, xb.y, xb.z, xb.w};
        float zs8[8];
        float acc = 0.0f;

        #pragma unroll
        for (int k = 0; k < DPG; k++) {
            float xk = xs8[k];

            // analytic bin guess on the linspace grid (error << 1 bin)
            int j = __float2int_rd((xk - di[k].x) * di[k].y);
            j = max(0, min(j, NBK - 2));

            // exact branchless +/-1 fixup:
            //   j == clip(searchsorted_left(xv, xk), 1, NBK-1) - 1
            const float* xq = xvs + k * NBK;
            float a0 = xq[j];
            float a1 = xq[j + 1];
            j += (int)(xk > a1);           // mutually exclusive with next (a0 < a1)
            j -= (int)(xk <= a0);
            j = max(0, min(j, NBK - 2));

            float4 e = tab[k * NBK + j];   // (x_l, slope, c_l, L)

            // u = c_l + slope*(x - x_l); t-clamp subsumes the reference's u-clip
            float u = fmaf(e.y, xk - e.x, e.z);
            float t = fmaf(2.0f, u, -1.0f);
            t = fminf(fmaxf(t, -0.99999f), 0.99999f);

            // branchless erfinv (Giles): evaluate both polys, select
            float w  = -__logf(fmaf(t, -t, 1.0f));   // w in (0, ~10.8]
            float wc = w - 2.5f;
            float wt = sqrtf(w) - 3.0f;

            float pc =               2.81022636e-08f;
            pc = fmaf(pc, wc,        3.43273939e-07f);
            pc = fmaf(pc, wc,       -3.5233877e-06f);
            pc = fmaf(pc, wc,       -4.39150654e-06f);
            pc = fmaf(pc, wc,        0.00021858087f);
            pc = fmaf(pc, wc,       -0.00125372503f);
            pc = fmaf(pc, wc,       -0.00417768164f);
            pc = fmaf(pc, wc,        0.246640727f);
            pc = fmaf(pc, wc,        1.50140941f);

            float pt =              -0.000200214257f;
            pt = fmaf(pt, wt,        0.000100950558f);
            pt = fmaf(pt, wt,        0.00134934322f);
            pt = fmaf(pt, wt,       -0.00367342844f);
            pt = fmaf(pt, wt,        0.00573950773f);
            pt = fmaf(pt, wt,       -0.0076224613f);
            pt = fmaf(pt, wt,        0.00943887047f);
            pt = fmaf(pt, wt,        1.00167406f);
            pt = fmaf(pt, wt,        2.83297682f);

            float p  = (w < 5.0f) ? pc : pt;
            float zz = 1.4142135623730951f * p * t;
            zz = fminf(fmaxf(zz, -10.0f), 10.0f);

            acc += fmaf(0.5f * zz, zz, e.w);
            zs8[k] = zz;
        }

        float4* zp = (float4*)(zout + (size_t)b * DIMS + d0);
        zp[0] = make_float4(zs8[0], zs8[1], zs8[2], zs8[3]);
        zp[1] = make_float4(zs8[4], zs8[5], zs8[6], zs8[7]);
        g_partial[(size_t)g * B + b] = acc;
    }
}

__global__ void mg_reduce(float* __restrict__ ld, int B)
{
    int i = blockIdx.x * blockDim.x + threadIdx.x;   // one thread = 4 samples
    int b = i * 4;
    if (b < B) {
        float4 s = make_float4(0.f, 0.f, 0.f, 0.f);
        #pragma unroll
        for (int g = 0; g < GROUPS; g++) {
            float4 v = *(const float4*)&g_partial[(size_t)g * B + b];
            s.x += v.x; s.y += v.y; s.z += v.z; s.w += v.w;
        }
        *(float4*)&ld[b] = s;
    }
}

extern "C" void kernel_launch(void* const* d_in, const int* in_sizes, int n_in,
                              void* d_out, int out_size)
{
    const float* x   = (const float*)d_in[0];
    const float* xv  = (const float*)d_in[1];
    const float* cdf = (const float*)d_in[2];
    float* out = (float*)d_out;

    const int B = in_sizes[0] / DIMS;
    const int spb = (B + NCHUNK - 1) / NCHUNK;
    const size_t smem = (size_t)DPG * NBK * 16 + (size_t)DPG * NBK * 4;  // 160000 B

    cudaFuncSetAttribute(mg_main, cudaFuncAttributeMaxDynamicSharedMemorySize, (int)smem);

    dim3 grid(NCHUNK, GROUPS);
    mg_main<<<grid, TPB, smem>>>(x, xv, cdf, out, B, spb);

    float* ld = out + (size_t)B * DIMS;
    int nred = (B + 3) / 4;
    mg_reduce<<<(nred + 511) / 512, 512>>>(ld, B);
}

// round 6
// speedup vs baseline: 1.1900x; 1.1500x over previous
#include <cuda_runtime.h>
#include <math.h>

// MarginalGaussianization forward on GB300 — issue-count-optimized version.
// Inputs: x [B,64] f32, x_values [64,1000] f32 (sorted linspace per row),
// cdf_values [64,1000] f32 (strictly increasing). Output: z [B,64] then log_det [B].
//
//  - 8 dim-groups x 18 sample-chunks = 144 blocks (single wave on 148 SMs).
//  - smem per block: payload float4[8][1000] (x_l, slope, c_l, L) = 128000 B
//                  + pair float2[8][1000] (xv[j], xv[j+1])        =  64000 B
//  - Hot path: 1-FMA bin guess, exact branchless +/-1 fixup via one LDS.64,
//    LDS.128 payload, erfinv central poly always + tail poly only when a lane
//    in the warp needs it (__any_sync), no dead clamps.

#define DIMS    64
#define NBK     1000
#define GROUPS  8
#define DPG     8
#define TPB     1024
#define NCHUNK  18
#define BMAX    262144

__device__ float g_partial[GROUPS * (size_t)BMAX];

__global__ __launch_bounds__(TPB)
void mg_main(const float* __restrict__ x,
             const float* __restrict__ xv,
             const float* __restrict__ cdf,
             float* __restrict__ zout,
             int B, int spb)
{
    extern __shared__ char smem_raw[];
    float4* tab  = (float4*)smem_raw;                        // [DPG][NBK] payload
    float2* pair = (float2*)(smem_raw + DPG * NBK * 16);     // [DPG][NBK] (xv[j], xv[j+1])
    __shared__ float2 dinfo_s[DPG];

    const int g  = blockIdx.y;
    const int d0 = g * DPG;

    // ---- Build per-bin payload + boundary-pair tables in shared memory ----
    for (int idx = threadIdx.x; idx < DPG * NBK; idx += TPB) {
        int k = idx / NBK;
        int j = idx - k * NBK;
        const float* xvk = xv  + (size_t)(d0 + k) * NBK;
        const float* ck  = cdf + (size_t)(d0 + k) * NBK;
        float xl = xvk[j];
        if (j < NBK - 1) {
            float xr = xvk[j + 1];
            float cl = ck[j],  cr = ck[j + 1];
            float denom = xr - xl + 1e-12f;
            float s  = (cr - cl) / denom;                    // matches reference math
            float ph = fmaxf(s, 1e-12f);                     // p_hat
            // term = log(p_hat) - log(phi + 1e-12)
            //      = [log(p_hat) + log(sqrt(2*pi))] + 0.5*z^2  (|z| <= 4.42, err < 5e-8)
            tab[k * NBK + j]  = make_float4(xl, s, cl, logf(ph) + 0.91893853320467274f);
            pair[k * NBK + j] = make_float2(xl, xr);
        } else {
            pair[k * NBK + j] = make_float2(xl, xl);         // never used (j clamped to NBK-2)
        }
    }
    if (threadIdx.x < DPG) {
        const float* xvk = xv + (size_t)(d0 + threadIdx.x) * NBK;
        float x0 = xvk[0], x1 = xvk[NBK - 1];
        float inv = (float)(NBK - 1) / (x1 - x0);
        dinfo_s[threadIdx.x] = make_float2(inv, -x0 * inv);  // j_guess = fma(x, inv, bias)
    }
    __syncthreads();

    float2 di[DPG];
    #pragma unroll
    for (int k = 0; k < DPG; k++) di[k] = dinfo_s[k];

    const int b0   = blockIdx.x * spb;
    const int bend = min(B, b0 + spb);

    for (int b = b0 + (int)threadIdx.x; b < bend; b += TPB) {
        const float4* xp = (const float4*)(x + (size_t)b * DIMS + d0);
        float4 xa = xp[0];
        float4 xb = xp[1];
        float xs8[8] = {xa.x, xa.y, xa.z, xa.w, xb.x, xb.y, xb.z, xb.w};
        float zs8[8];
        float acc = 0.0f;

        #pragma unroll
        for (int k = 0; k < DPG; k++) {
            float xk = xs8[k];

            // analytic bin guess on the linspace grid (within +/-1 of truth)
            int j = __float2int_rd(fmaf(xk, di[k].x, di[k].y));
            j = max(0, min(j, NBK - 2));

            // exact branchless +/-1 fixup:
            //   j == clip(searchsorted_left(xv, xk), 1, NBK-1) - 1
            float2 pr = pair[k * NBK + j];                   // (xv[j], xv[j+1])
            j += (int)(xk > pr.y);                           // mutually exclusive (pr.x < pr.y)
            j -= (int)(xk <= pr.x);
            j = max(0, min(j, NBK - 2));

            float4 e = tab[k * NBK + j];                     // (x_l, slope, c_l, L)

            // u = c_l + slope*(x - x_l); t-clamp subsumes the reference's u-clip
            float u = fmaf(e.y, xk - e.x, e.z);
            float t = fmaf(2.0f, u, -1.0f);
            t = fminf(fmaxf(t, -0.99999f), 0.99999f);

            // erfinv (Giles). Central poly always; tail only if some lane needs it.
            float w  = -__logf(fmaf(t, -t, 1.0f));           // w in (0, ~10.82]
            float wc = w - 2.5f;

            float p =               2.81022636e-08f;
            p = fmaf(p, wc,         3.43273939e-07f);
            p = fmaf(p, wc,        -3.5233877e-06f);
            p = fmaf(p, wc,        -4.39150654e-06f);
            p = fmaf(p, wc,         0.00021858087f);
            p = fmaf(p, wc,        -0.00125372503f);
            p = fmaf(p, wc,        -0.00417768164f);
            p = fmaf(p, wc,         0.246640727f);
            p = fmaf(p, wc,         1.50140941f);

            if (__any_sync(__activemask(), w >= 5.0f)) {
                float wt = sqrtf(w) - 3.0f;
                float pt =              -0.000200214257f;
                pt = fmaf(pt, wt,        0.000100950558f);
                pt = fmaf(pt, wt,        0.00134934322f);
                pt = fmaf(pt, wt,       -0.00367342844f);
                pt = fmaf(pt, wt,        0.00573950773f);
                pt = fmaf(pt, wt,       -0.0076224613f);
                pt = fmaf(pt, wt,        0.00943887047f);
                pt = fmaf(pt, wt,        1.00167406f);
                pt = fmaf(pt, wt,        2.83297682f);
                p = (w < 5.0f) ? p : pt;
            }

            // |z| <= 4.42 < 10, so the reference's z-clip never binds — omitted.
            float zz = 1.4142135623730951f * p * t;

            acc += fmaf(0.5f * zz, zz, e.w);
            zs8[k] = zz;
        }

        float4* zp = (float4*)(zout + (size_t)b * DIMS + d0);
        zp[0] = make_float4(zs8[0], zs8[1], zs8[2], zs8[3]);
        zp[1] = make_float4(zs8[4], zs8[5], zs8[6], zs8[7]);
        g_partial[(size_t)g * B + b] = acc;
    }
}

__global__ __launch_bounds__(1024)
void mg_reduce(float* __restrict__ ld, int B)
{
    int b = blockIdx.x * blockDim.x + threadIdx.x;
    if (b < B) {
        float s = 0.0f;
        #pragma unroll
        for (int g = 0; g < GROUPS; g++) s += g_partial[(size_t)g * B + b];
        ld[b] = s;
    }
}

extern "C" void kernel_launch(void* const* d_in, const int* in_sizes, int n_in,
                              void* d_out, int out_size)
{
    const float* x   = (const float*)d_in[0];
    const float* xv  = (const float*)d_in[1];
    const float* cdf = (const float*)d_in[2];
    float* out = (float*)d_out;

    const int B = in_sizes[0] / DIMS;
    const int spb = (B + NCHUNK - 1) / NCHUNK;
    const size_t smem = (size_t)DPG * NBK * 16 + (size_t)DPG * NBK * 8;  // 192000 B

    cudaFuncSetAttribute(mg_main, cudaFuncAttributeMaxDynamicSharedMemorySize, (int)smem);

    dim3 grid(NCHUNK, GROUPS);
    mg_main<<<grid, TPB, smem>>>(x, xv, cdf, out, B, spb);

    float* ld = out + (size_t)B * DIMS;
    mg_reduce<<<(B + 1023) / 1024, 1024>>>(ld, B);
}